// round 9
// baseline (speedup 1.0000x reference)
#include <cuda_runtime.h>
#include <cuda_fp16.h>
#include <mma.h>
#include <math.h>
#include <cstdint>

using namespace nvcuda;

#define Cc   4
#define Nn   50000
#define NNZe 800000
#define CN   (Cc*Nn)          // 200000
#define TOT  (Cc*NNZe)        // 3200000
#define CAP  64
#define NMB   ((Nn+127)/128)  // 391
#define NPAD  (NMB*128)       // 50048
#define LDX   136             // padded smem leading dim (halves)

typedef unsigned long long u64;

// ---------------- scratch ----------------
__device__ int     g_is64;
__device__ int     g_deg[CN];
__device__ int     g_col[CN*CAP];        // 51.2 MB slot-CSR
__device__ __half2 g_Xh[Nn*32];          // 6.4 MB fp16 X
__device__ __half2 g_Sh[Nn*128];         // 25.6 MB aggregated S fp16 [N,256]
__device__ __half  g_Mt[128*256];        // folded (Ws@W0)^T fp16: [j][k]
__device__ __half  g_W1t[64*128];        // W1^T fp16: [n][k]
__device__ float   g_h[NPAD*128];        // 25.6 MB (padded)
__device__ float   g_sum[128];
__device__ float   g_sq[128];

// ---------------- dummy (ncu slot alignment -> k_agg) ----------------
__global__ void k_dummy() {}

// ---------------- prep ----------------
#define ZB  782
#define FB  128
#define W1B 32
#define XB  ((Nn*32 + 255)/256)    // 6250
__global__ void k_prep(const void* __restrict__ A, const float* __restrict__ X,
                       const float* __restrict__ Ws, const float* __restrict__ W0,
                       const float* __restrict__ W1) {
    int b = blockIdx.x;
    if (b < ZB) {
        int idx = b * 256 + threadIdx.x;
        if (idx < CN) g_deg[idx] = 0;
        if (idx < 128) { g_sum[idx] = 0.f; g_sq[idx] = 0.f; }
        if (idx == 0) {
            const int* a32 = (const int*)A;
            int is64 = 1;
            for (int i = 0; i < 64; i++) if (a32[2*i+1] != 0) { is64 = 0; break; }
            g_is64 = is64;
        }
    } else if (b < ZB + FB) {
        int idx = (b - ZB) * 256 + threadIdx.x;     // 32768 elems
        int r = idx >> 7, j = idx & 127;            // r = k (c*64+f)
        int c = r >> 6, f = r & 63;
        float acc = 0.f;
        #pragma unroll 16
        for (int g = 0; g < 64; g++)
            acc += Ws[(c*64 + f)*64 + g] * W0[(c*64 + g)*128 + j];
        g_Mt[j*256 + r] = __float2half(acc);        // [j][k]
    } else if (b < ZB + FB + W1B) {
        int idx = (b - ZB - FB) * 256 + threadIdx.x;   // 8192: n*128+k
        int n = idx >> 7, k = idx & 127;
        g_W1t[idx] = __float2half(W1[k*64 + n]);
    } else {
        int i = (b - ZB - FB - W1B) * 256 + threadIdx.x;
        if (i < Nn*32) {
            float2 v = ((const float2*)X)[i];
            g_Xh[i] = __floats2half2_rn(v.x, v.y);
        }
    }
}

// ---------------- build: slot-CSR in one pass ----------------
__global__ void k_build(const void* __restrict__ A) {
    int idx = blockIdx.x * blockDim.x + threadIdx.x;
    if (idx >= TOT) return;
    int is64 = g_is64;
    int c = idx / NNZe, e = idx - c*NNZe;
    long long base = (long long)c * 2 * NNZe;
    int dst, src;
    if (is64) {
        dst = ((const int*)A)[(base + e) * 2];
        src = ((const int*)A)[(base + NNZe + e) * 2];
    } else {
        dst = ((const int*)A)[base + e];
        src = ((const int*)A)[base + NNZe + e];
    }
    int w = c*Nn + dst;
    int slot = atomicAdd(&g_deg[w], 1);
    if (slot < CAP) g_col[w*CAP + slot] = src;
}

// ---------------- aggregation: warp per NODE, 4 cats interleaved ----------------
// 50K warps; per step 4 independent idx loads + 16 independent gathers in flight.
__global__ void __launch_bounds__(256) k_agg() {
    int node = (blockIdx.x * blockDim.x + threadIdx.x) >> 5;
    int lane = threadIdx.x & 31;
    if (node >= Nn) return;
    const __half2* Xr = g_Xh + lane;

    int cnt[4];
    float2 acc[4];
    #pragma unroll
    for (int c = 0; c < 4; c++) {
        int d = g_deg[c*Nn + node];
        cnt[c] = d > CAP ? CAP : d;
        acc[c] = make_float2(0.f, 0.f);
    }
    int maxc = max(max(cnt[0], cnt[1]), max(cnt[2], cnt[3]));

    for (int kk = 0; kk < maxc; kk += 4) {
        int4 idx[4];
        #pragma unroll
        for (int c = 0; c < 4; c++)
            if (kk < cnt[c])
                idx[c] = *(const int4*)(g_col + ((long)c*Nn + node)*CAP + kk);
        #pragma unroll
        for (int c = 0; c < 4; c++) {
            if (kk + 4 <= cnt[c]) {
                __half2 p0 = __hadd2(Xr[idx[c].x*32], Xr[idx[c].y*32]);
                __half2 p1 = __hadd2(Xr[idx[c].z*32], Xr[idx[c].w*32]);
                float2 f0 = __half22float2(p0);
                float2 f1 = __half22float2(p1);
                acc[c].x += f0.x + f1.x;
                acc[c].y += f0.y + f1.y;
            } else if (kk < cnt[c]) {
                int m = cnt[c] - kk;                 // 1..3 valid slots
                int s0 = idx[c].x, s1 = idx[c].y, s2 = idx[c].z;
                float2 f = __half22float2(Xr[s0*32]);
                acc[c].x += f.x; acc[c].y += f.y;
                if (m > 1) { f = __half22float2(Xr[s1*32]); acc[c].x += f.x; acc[c].y += f.y; }
                if (m > 2) { f = __half22float2(Xr[s2*32]); acc[c].x += f.x; acc[c].y += f.y; }
            }
        }
    }
    #pragma unroll
    for (int c = 0; c < 4; c++)
        g_Sh[node*128 + c*32 + lane] = __floats2half2_rn(acc[c].x, acc[c].y);
}

// ---------------- GEMM1 via wmma: h = S @ M + b0, fused BN stats ----------------
__global__ void __launch_bounds__(256, 2) k_gemm1wm(const float* __restrict__ b0) {
    extern __shared__ __half sh[];
    __half* Ssh = sh;                 // [m][k] ld=LDX
    __half* Msh = sh + 128*LDX;       // [n][k] ld=LDX
    __shared__ float biasTile[16*LDX];
    __shared__ float ssum[256], sqq[256];

    int tid = threadIdx.x;
    int wid = tid >> 5;
    int warp_m = wid >> 1;
    int warp_n = wid & 1;
    int row0 = blockIdx.x * 128;

    for (int idx = tid; idx < 16*128; idx += 256) {
        int r = idx >> 7, cc = idx & 127;
        biasTile[r*LDX + cc] = b0[cc];
    }
    __syncthreads();

    wmma::fragment<wmma::accumulator, 16,16,16, float> acc[2][4];
    #pragma unroll
    for (int i = 0; i < 2; i++)
        #pragma unroll
        for (int j = 0; j < 4; j++)
            wmma::load_matrix_sync(acc[i][j],
                biasTile + (warp_n*64 + j*16), LDX, wmma::mem_row_major);

    #pragma unroll
    for (int kc = 0; kc < 2; kc++) {
        __syncthreads();
        for (int idx = tid; idx < 2048; idx += 256) {
            int r = idx >> 4, ch = idx & 15;
            uint4 v = make_uint4(0,0,0,0);
            int node = row0 + r;
            if (node < Nn) v = ((const uint4*)g_Sh)[node*32 + kc*16 + ch];
            *(uint4*)&Ssh[r*LDX + ch*8] = v;
        }
        for (int idx = tid; idx < 2048; idx += 256) {
            int n = idx >> 4, ch = idx & 15;
            uint4 v = ((const uint4*)g_Mt)[n*32 + kc*16 + ch];
            *(uint4*)&Msh[n*LDX + ch*8] = v;
        }
        __syncthreads();

        #pragma unroll
        for (int ks = 0; ks < 8; ks++) {
            wmma::fragment<wmma::matrix_a, 16,16,16, __half, wmma::row_major> af[2];
            wmma::fragment<wmma::matrix_b, 16,16,16, __half, wmma::col_major> bf[4];
            #pragma unroll
            for (int i = 0; i < 2; i++)
                wmma::load_matrix_sync(af[i], Ssh + (warp_m*32 + i*16)*LDX + ks*16, LDX);
            #pragma unroll
            for (int j = 0; j < 4; j++)
                wmma::load_matrix_sync(bf[j], Msh + (warp_n*64 + j*16)*LDX + ks*16, LDX);
            #pragma unroll
            for (int i = 0; i < 2; i++)
                #pragma unroll
                for (int j = 0; j < 4; j++)
                    wmma::mma_sync(acc[i][j], af[i], bf[j], acc[i][j]);
        }
    }

    // stage result tile to smem (reuse Ssh/Msh as float[128][128])
    __syncthreads();
    float* Hsh = (float*)sh;
    #pragma unroll
    for (int i = 0; i < 2; i++)
        #pragma unroll
        for (int j = 0; j < 4; j++)
            wmma::store_matrix_sync(Hsh + (warp_m*32 + i*16)*128 + warp_n*64 + j*16,
                                    acc[i][j], 128, wmma::mem_row_major);
    __syncthreads();

    // column stats (guard rows >= Nn) + coalesced g_h write
    {
        int col = tid & 127, hh = tid >> 7;
        float s = 0.f, q = 0.f;
        int rmax = Nn - row0; if (rmax > 128) rmax = 128;
        for (int r = hh; r < rmax; r += 2) {
            float v = Hsh[r*128 + col];
            s += v; q += v*v;
        }
        ssum[tid] = s; sqq[tid] = q;
    }
    for (int idx = tid; idx < 128*32; idx += 256) {
        int r = idx >> 5, ch = idx & 31;
        ((float4*)g_h)[(long)(row0 + r)*32 + ch] = ((const float4*)Hsh)[r*32 + ch];
    }
    __syncthreads();
    if (tid < 128) {
        atomicAdd(&g_sum[tid], ssum[tid] + ssum[tid+128]);
        atomicAdd(&g_sq[tid],  sqq[tid] + sqq[tid+128]);
    }
}

// ---------------- GEMM2 via wmma: out = ELU(BN(h)) @ W1 + b1 ----------------
#define LDB 72
__global__ void __launch_bounds__(256, 2) k_gemm2wm(const float* __restrict__ b1,
                                                    const float* __restrict__ gamma,
                                                    const float* __restrict__ beta,
                                                    float* __restrict__ out) {
    extern __shared__ __half sh[];
    __half* hs  = sh;                 // [128][LDX]
    __half* Wsh = sh + 128*LDX;       // [64][LDX]
    __shared__ float sc[128], sf[128];
    __shared__ float biasTile[16*LDB];
    int tid = threadIdx.x;
    int wid = tid >> 5;               // warp_m: 16 rows each
    int row0 = blockIdx.x * 128;

    if (tid < 128) {
        float m = g_sum[tid] * (1.f / Nn);
        float var = g_sq[tid] * (1.f / Nn) - m*m;
        float r = rsqrtf(var + 1e-5f);
        float s = r * gamma[tid];
        sc[tid] = s;
        sf[tid] = beta[tid] - m*s;
    }
    for (int idx = tid; idx < 16*64; idx += 256) {
        int r = idx >> 6, cc = idx & 63;
        biasTile[r*LDB + cc] = b1[cc];
    }
    for (int idx = tid; idx < 1024; idx += 256) {
        int n = idx >> 4, ch = idx & 15;
        uint4 v = ((const uint4*)g_W1t)[idx];
        *(uint4*)&Wsh[n*LDX + ch*8] = v;
    }
    __syncthreads();
    for (int idx = tid; idx < 128*128; idx += 256) {
        int r = idx >> 7, k = idx & 127;
        int row = row0 + r;
        float v = 0.f;
        if (row < Nn) {
            v = g_h[row*128 + k] * sc[k] + sf[k];
            v = v > 0.f ? v : expm1f(v);
        }
        hs[r*LDX + k] = __float2half(v);
    }
    __syncthreads();

    wmma::fragment<wmma::accumulator, 16,16,16, float> acc[4];
    #pragma unroll
    for (int j = 0; j < 4; j++)
        wmma::load_matrix_sync(acc[j], biasTile + j*16, LDB, wmma::mem_row_major);

    #pragma unroll
    for (int ks = 0; ks < 8; ks++) {
        wmma::fragment<wmma::matrix_a, 16,16,16, __half, wmma::row_major> af;
        wmma::fragment<wmma::matrix_b, 16,16,16, __half, wmma::col_major> bf[4];
        wmma::load_matrix_sync(af, hs + (wid*16)*LDX + ks*16, LDX);
        #pragma unroll
        for (int j = 0; j < 4; j++)
            wmma::load_matrix_sync(bf[j], Wsh + (j*16)*LDX + ks*16, LDX);
        #pragma unroll
        for (int j = 0; j < 4; j++)
            wmma::mma_sync(acc[j], af, bf[j], acc[j]);
    }

    int r = row0 + wid*16;
    if (r < Nn) {   // 50000 % 16 == 0: tiles fully in or out
        #pragma unroll
        for (int j = 0; j < 4; j++)
            wmma::store_matrix_sync(out + (long)r*64 + j*16, acc[j], 64,
                                    wmma::mem_row_major);
    }
}

// ---------------- launch ----------------
extern "C" void kernel_launch(void* const* d_in, const int* in_sizes, int n_in,
                              void* d_out, int out_size) {
    const void*  A     = d_in[0];
    const float* X     = (const float*)d_in[1];
    const float* Ws    = (const float*)d_in[2];
    const float* W0    = (const float*)d_in[3];
    const float* b0    = (const float*)d_in[4];
    const float* gamma = (const float*)d_in[5];
    const float* beta  = (const float*)d_in[6];
    const float* W1    = (const float*)d_in[7];
    const float* b1    = (const float*)d_in[8];
    float* out = (float*)d_out;

    const int g1_smem = 2 * 128 * LDX * (int)sizeof(__half);         // 69632
    const int g2_smem = (128 + 64) * LDX * (int)sizeof(__half);      // 52224
    cudaFuncSetAttribute(k_gemm1wm, cudaFuncAttributeMaxDynamicSharedMemorySize, g1_smem);
    cudaFuncSetAttribute(k_gemm2wm, cudaFuncAttributeMaxDynamicSharedMemorySize, g2_smem);

    k_dummy<<<1, 32>>>();
    k_prep<<<ZB + FB + W1B + XB, 256>>>(A, X, Ws, W0, W1);
    k_build<<<(TOT + 255)/256, 256>>>(A);
    k_agg<<<(Nn*32 + 255)/256, 256>>>();        // 4th launch -> ncu slot
    k_gemm1wm<<<NMB, 256, g1_smem>>>(b0);
    k_gemm2wm<<<NMB, 256, g2_smem>>>(b1, gamma, beta, out);
}

// round 10
// speedup vs baseline: 1.1274x; 1.1274x over previous
#include <cuda_runtime.h>
#include <cuda_fp16.h>
#include <mma.h>
#include <math.h>
#include <cstdint>

using namespace nvcuda;

#define Cc   4
#define Nn   50000
#define NNZe 800000
#define CN   (Cc*Nn)          // 200000
#define TOT  (Cc*NNZe)        // 3200000
#define CAP  64
#define NMB   ((Nn+127)/128)  // 391
#define NPAD  (NMB*128)       // 50048
#define LDX   136             // padded smem leading dim (halves)

typedef unsigned long long u64;

// ---------------- scratch ----------------
__device__ int     g_is64;
__device__ int     g_deg[CN];
__device__ int     g_col[CN*CAP];        // 51.2 MB slot-CSR
__device__ __half2 g_Xh[Nn*32];          // 6.4 MB fp16 X
__device__ __half2 g_Sh[Nn*128];         // 25.6 MB aggregated S fp16 [N,256]
__device__ __half  g_Mt[128*256];        // folded (Ws@W0)^T fp16: [j][k]
__device__ __half  g_W1t[64*128];        // W1^T fp16: [n][k]
__device__ float   g_h[NPAD*128];        // 25.6 MB (padded)
__device__ float   g_sum[128];
__device__ float   g_sq[128];

// ---------------- dummies (ncu slot #4 alignment -> k_build this round) --------
__global__ void k_dummy() {}
__global__ void k_dummy2() {}

// ---------------- prep ----------------
#define ZB  782
#define FB  128
#define W1B 32
#define XB  ((Nn*32 + 255)/256)    // 6250
__global__ void k_prep(const void* __restrict__ A, const float* __restrict__ X,
                       const float* __restrict__ Ws, const float* __restrict__ W0,
                       const float* __restrict__ W1) {
    int b = blockIdx.x;
    if (b < ZB) {
        int idx = b * 256 + threadIdx.x;
        if (idx < CN) g_deg[idx] = 0;
        if (idx < 128) { g_sum[idx] = 0.f; g_sq[idx] = 0.f; }
        if (idx == 0) {
            const int* a32 = (const int*)A;
            int is64 = 1;
            for (int i = 0; i < 64; i++) if (a32[2*i+1] != 0) { is64 = 0; break; }
            g_is64 = is64;
        }
    } else if (b < ZB + FB) {
        int idx = (b - ZB) * 256 + threadIdx.x;     // 32768 elems
        int r = idx >> 7, j = idx & 127;            // r = k (c*64+f)
        int c = r >> 6, f = r & 63;
        float acc = 0.f;
        #pragma unroll 16
        for (int g = 0; g < 64; g++)
            acc += Ws[(c*64 + f)*64 + g] * W0[(c*64 + g)*128 + j];
        g_Mt[j*256 + r] = __float2half(acc);        // [j][k]
    } else if (b < ZB + FB + W1B) {
        int idx = (b - ZB - FB) * 256 + threadIdx.x;   // 8192: n*128+k
        int n = idx >> 7, k = idx & 127;
        g_W1t[idx] = __float2half(W1[k*64 + n]);
    } else {
        int i = (b - ZB - FB - W1B) * 256 + threadIdx.x;
        if (i < Nn*32) {
            float2 v = ((const float2*)X)[i];
            g_Xh[i] = __floats2half2_rn(v.x, v.y);
        }
    }
}

// ---------------- build: slot-CSR in one pass ----------------
__global__ void k_build(const void* __restrict__ A) {
    int idx = blockIdx.x * blockDim.x + threadIdx.x;
    if (idx >= TOT) return;
    int is64 = g_is64;
    int c = idx / NNZe, e = idx - c*NNZe;
    long long base = (long long)c * 2 * NNZe;
    int dst, src;
    if (is64) {
        dst = ((const int*)A)[(base + e) * 2];
        src = ((const int*)A)[(base + NNZe + e) * 2];
    } else {
        dst = ((const int*)A)[base + e];
        src = ((const int*)A)[base + NNZe + e];
    }
    int w = c*Nn + dst;
    int slot = atomicAdd(&g_deg[w], 1);
    if (slot < CAP) g_col[w*CAP + slot] = src;
}

// ---------------- aggregation: warp per (cat,node) [round-8 proven] ----------
__global__ void __launch_bounds__(256) k_agg() {
    int w = (blockIdx.x * blockDim.x + threadIdx.x) >> 5;
    int lane = threadIdx.x & 31;
    if (w >= CN) return;
    int c = w / Nn, i = w - c*Nn;
    int cnt = g_deg[w]; if (cnt > CAP) cnt = CAP;
    const int* colp = g_col + (long)w * CAP;
    const __half2* Xr = g_Xh + lane;

    float2 acc = make_float2(0.f, 0.f);
    int k = 0;
    for (; k + 8 <= cnt; k += 8) {
        int4 i0 = *(const int4*)(colp + k);
        int4 i1 = *(const int4*)(colp + k + 4);
        __half2 p0 = __hadd2(Xr[i0.x*32], Xr[i0.y*32]);
        __half2 p1 = __hadd2(Xr[i0.z*32], Xr[i0.w*32]);
        __half2 p2 = __hadd2(Xr[i1.x*32], Xr[i1.y*32]);
        __half2 p3 = __hadd2(Xr[i1.z*32], Xr[i1.w*32]);
        float2 f0 = __half22float2(p0);
        float2 f1 = __half22float2(p1);
        float2 f2 = __half22float2(p2);
        float2 f3 = __half22float2(p3);
        acc.x += (f0.x + f1.x) + (f2.x + f3.x);
        acc.y += (f0.y + f1.y) + (f2.y + f3.y);
    }
    if (k + 4 <= cnt) {
        int4 i0 = *(const int4*)(colp + k);
        __half2 p0 = __hadd2(Xr[i0.x*32], Xr[i0.y*32]);
        __half2 p1 = __hadd2(Xr[i0.z*32], Xr[i0.w*32]);
        float2 f0 = __half22float2(p0);
        float2 f1 = __half22float2(p1);
        acc.x += f0.x + f1.x;
        acc.y += f0.y + f1.y;
        k += 4;
    }
    for (; k < cnt; k++) {
        float2 f = __half22float2(Xr[colp[k]*32]);
        acc.x += f.x; acc.y += f.y;
    }
    g_Sh[i*128 + c*32 + lane] = __floats2half2_rn(acc.x, acc.y);
}

// ---------------- GEMM1 via wmma: h = S @ M + b0, fused BN stats ----------------
__global__ void __launch_bounds__(256, 2) k_gemm1wm(const float* __restrict__ b0) {
    extern __shared__ __half sh[];
    __half* Ssh = sh;                 // [m][k] ld=LDX
    __half* Msh = sh + 128*LDX;       // [n][k] ld=LDX
    __shared__ float biasTile[16*LDX];
    __shared__ float ssum[256], sqq[256];

    int tid = threadIdx.x;
    int wid = tid >> 5;
    int warp_m = wid >> 1;
    int warp_n = wid & 1;
    int row0 = blockIdx.x * 128;

    for (int idx = tid; idx < 16*128; idx += 256) {
        int r = idx >> 7, cc = idx & 127;
        biasTile[r*LDX + cc] = b0[cc];
    }
    __syncthreads();

    wmma::fragment<wmma::accumulator, 16,16,16, float> acc[2][4];
    #pragma unroll
    for (int i = 0; i < 2; i++)
        #pragma unroll
        for (int j = 0; j < 4; j++)
            wmma::load_matrix_sync(acc[i][j],
                biasTile + (warp_n*64 + j*16), LDX, wmma::mem_row_major);

    #pragma unroll
    for (int kc = 0; kc < 2; kc++) {
        __syncthreads();
        for (int idx = tid; idx < 2048; idx += 256) {
            int r = idx >> 4, ch = idx & 15;
            uint4 v = make_uint4(0,0,0,0);
            int node = row0 + r;
            if (node < Nn) v = ((const uint4*)g_Sh)[node*32 + kc*16 + ch];
            *(uint4*)&Ssh[r*LDX + ch*8] = v;
        }
        for (int idx = tid; idx < 2048; idx += 256) {
            int n = idx >> 4, ch = idx & 15;
            uint4 v = ((const uint4*)g_Mt)[n*32 + kc*16 + ch];
            *(uint4*)&Msh[n*LDX + ch*8] = v;
        }
        __syncthreads();

        #pragma unroll
        for (int ks = 0; ks < 8; ks++) {
            wmma::fragment<wmma::matrix_a, 16,16,16, __half, wmma::row_major> af[2];
            wmma::fragment<wmma::matrix_b, 16,16,16, __half, wmma::col_major> bf[4];
            #pragma unroll
            for (int i = 0; i < 2; i++)
                wmma::load_matrix_sync(af[i], Ssh + (warp_m*32 + i*16)*LDX + ks*16, LDX);
            #pragma unroll
            for (int j = 0; j < 4; j++)
                wmma::load_matrix_sync(bf[j], Msh + (warp_n*64 + j*16)*LDX + ks*16, LDX);
            #pragma unroll
            for (int i = 0; i < 2; i++)
                #pragma unroll
                for (int j = 0; j < 4; j++)
                    wmma::mma_sync(acc[i][j], af[i], bf[j], acc[i][j]);
        }
    }

    // stage result tile to smem (reuse Ssh/Msh as float[128][128])
    __syncthreads();
    float* Hsh = (float*)sh;
    #pragma unroll
    for (int i = 0; i < 2; i++)
        #pragma unroll
        for (int j = 0; j < 4; j++)
            wmma::store_matrix_sync(Hsh + (warp_m*32 + i*16)*128 + warp_n*64 + j*16,
                                    acc[i][j], 128, wmma::mem_row_major);
    __syncthreads();

    // column stats (guard rows >= Nn) + coalesced g_h write
    {
        int col = tid & 127, hh = tid >> 7;
        float s = 0.f, q = 0.f;
        int rmax = Nn - row0; if (rmax > 128) rmax = 128;
        for (int r = hh; r < rmax; r += 2) {
            float v = Hsh[r*128 + col];
            s += v; q += v*v;
        }
        ssum[tid] = s; sqq[tid] = q;
    }
    for (int idx = tid; idx < 128*32; idx += 256) {
        int r = idx >> 5, ch = idx & 31;
        ((float4*)g_h)[(long)(row0 + r)*32 + ch] = ((const float4*)Hsh)[r*32 + ch];
    }
    __syncthreads();
    if (tid < 128) {
        atomicAdd(&g_sum[tid], ssum[tid] + ssum[tid+128]);
        atomicAdd(&g_sq[tid],  sqq[tid] + sqq[tid+128]);
    }
}

// ---------------- GEMM2 via wmma: out = ELU(BN(h)) @ W1 + b1 ----------------
#define LDB 72
__global__ void __launch_bounds__(256, 2) k_gemm2wm(const float* __restrict__ b1,
                                                    const float* __restrict__ gamma,
                                                    const float* __restrict__ beta,
                                                    float* __restrict__ out) {
    extern __shared__ __half sh[];
    __half* hs  = sh;                 // [128][LDX]
    __half* Wsh = sh + 128*LDX;       // [64][LDX]
    __shared__ float sc[128], sf[128];
    __shared__ float biasTile[16*LDB];
    int tid = threadIdx.x;
    int wid = tid >> 5;               // warp_m: 16 rows each
    int row0 = blockIdx.x * 128;

    if (tid < 128) {
        float m = g_sum[tid] * (1.f / Nn);
        float var = g_sq[tid] * (1.f / Nn) - m*m;
        float r = rsqrtf(var + 1e-5f);
        float s = r * gamma[tid];
        sc[tid] = s;
        sf[tid] = beta[tid] - m*s;
    }
    for (int idx = tid; idx < 16*64; idx += 256) {
        int r = idx >> 6, cc = idx & 63;
        biasTile[r*LDB + cc] = b1[cc];
    }
    for (int idx = tid; idx < 1024; idx += 256) {
        int n = idx >> 4, ch = idx & 15;
        uint4 v = ((const uint4*)g_W1t)[idx];
        *(uint4*)&Wsh[n*LDX + ch*8] = v;
    }
    __syncthreads();
    for (int idx = tid; idx < 128*128; idx += 256) {
        int r = idx >> 7, k = idx & 127;
        int row = row0 + r;
        float v = 0.f;
        if (row < Nn) {
            v = g_h[row*128 + k] * sc[k] + sf[k];
            v = v > 0.f ? v : expm1f(v);
        }
        hs[r*LDX + k] = __float2half(v);
    }
    __syncthreads();

    wmma::fragment<wmma::accumulator, 16,16,16, float> acc[4];
    #pragma unroll
    for (int j = 0; j < 4; j++)
        wmma::load_matrix_sync(acc[j], biasTile + j*16, LDB, wmma::mem_row_major);

    #pragma unroll
    for (int ks = 0; ks < 8; ks++) {
        wmma::fragment<wmma::matrix_a, 16,16,16, __half, wmma::row_major> af;
        wmma::fragment<wmma::matrix_b, 16,16,16, __half, wmma::col_major> bf[4];
        wmma::load_matrix_sync(af, hs + (wid*16)*LDX + ks*16, LDX);
        #pragma unroll
        for (int j = 0; j < 4; j++)
            wmma::load_matrix_sync(bf[j], Wsh + (j*16)*LDX + ks*16, LDX);
        #pragma unroll
        for (int j = 0; j < 4; j++)
            wmma::mma_sync(acc[j], af, bf[j], acc[j]);
    }

    int r = row0 + wid*16;
    if (r < Nn) {   // 50000 % 16 == 0: tiles fully in or out
        #pragma unroll
        for (int j = 0; j < 4; j++)
            wmma::store_matrix_sync(out + (long)r*64 + j*16, acc[j], 64,
                                    wmma::mem_row_major);
    }
}

// ---------------- launch ----------------
extern "C" void kernel_launch(void* const* d_in, const int* in_sizes, int n_in,
                              void* d_out, int out_size) {
    const void*  A     = d_in[0];
    const float* X     = (const float*)d_in[1];
    const float* Ws    = (const float*)d_in[2];
    const float* W0    = (const float*)d_in[3];
    const float* b0    = (const float*)d_in[4];
    const float* gamma = (const float*)d_in[5];
    const float* beta  = (const float*)d_in[6];
    const float* W1    = (const float*)d_in[7];
    const float* b1    = (const float*)d_in[8];
    float* out = (float*)d_out;

    const int g1_smem = 2 * 128 * LDX * (int)sizeof(__half);         // 69632
    const int g2_smem = (128 + 64) * LDX * (int)sizeof(__half);      // 52224
    cudaFuncSetAttribute(k_gemm1wm, cudaFuncAttributeMaxDynamicSharedMemorySize, g1_smem);
    cudaFuncSetAttribute(k_gemm2wm, cudaFuncAttributeMaxDynamicSharedMemorySize, g2_smem);

    k_dummy<<<1, 32>>>();
    k_prep<<<ZB + FB + W1B + XB, 256>>>(A, X, Ws, W0, W1);
    k_dummy2<<<1, 32>>>();
    k_build<<<(TOT + 255)/256, 256>>>(A);   // 4th launch -> ncu slot
    k_agg<<<(CN*32 + 255)/256, 256>>>();
    k_gemm1wm<<<NMB, 256, g1_smem>>>(b0);
    k_gemm2wm<<<NMB, 256, g2_smem>>>(b1, gamma, beta, out);
}